// round 12
// baseline (speedup 1.0000x reference)
#include <cuda_runtime.h>

// DTWLoss B=64, T=1024. Warp-pipelined column-sweep DP with fused path loss.
// 2 CTAs per batch (rows 0-511 / 512-1023), 8 warps x 32 lanes x 2 rows each.
// 16-stage pipeline, CW=16 with skew-2 chunk gating (consumer chunk cc waits
// for producer chunk cc+2 to FINISH; lane skew 31 cols, producer chunk cc+2
// covers boundary cols <= 16cc+17 >= needed 16cc+15). All sync is blocking
// rendezvous bar.sync (R8-safe). Cross-CTA: gmem boundary + self-resetting
// acquire/release flags with one-chunk prefetch (latency hidden by the body).
// Inner loop identical to R8 (fastest measured).

#define Tn 1024
#define Bn 64
#define CW 16
#define NWARP 8
#define NTH 256
#define NCHUNK 66              // chunks 0..65; last has 15 steps (total 1055)
#define INFV 1e30f

__device__ float2   g_bnd[Bn][Tn + 96];    // row-511 boundary; +32 front pad
__device__ unsigned g_flag[Bn][72];        // per-chunk ready flags (self-reset)
__device__ float2   g_dummy[2 * Bn][32];   // gmem store sink (lo warp7, lanes!=31)
__device__ float    g_losses[Bn];
__device__ unsigned g_count;               // zero-init; last CTA resets

__device__ __forceinline__ unsigned ld_acq(const unsigned* p) {
    unsigned v;
    asm volatile("ld.acquire.gpu.u32 %0, [%1];" : "=r"(v) : "l"(p) : "memory");
    return v;
}
__device__ __forceinline__ void st_rel(unsigned* p, unsigned v) {
    asm volatile("st.release.gpu.u32 [%0], %1;" :: "l"(p), "r"(v) : "memory");
}
__device__ __forceinline__ float fsqrt_ap(float x) {
    float r;
    asm("sqrt.approx.f32 %0, %1;" : "=f"(r) : "f"(x));
    return r;
}
#define BARSYNC(id) asm volatile("bar.sync %0, 64;" :: "r"(id) : "memory")

// One 16(or 15)-step chunk. GOUT: boundary store goes to gmem (lo warp7).
// Body identical to R8's fastest inner loop.
template<int NSTEPS, bool GOUT>
__device__ __forceinline__ void run_chunk(
    int s0, bool is_lane0, bool is_lane31,
    const float2* __restrict__ bp, const float2* __restrict__ qp,
    float2* outp, int msk, float2* sinkp,
    float px0, float py0, float px1, float py1, float sc0, float sc1,
    float& c0, float& c1, float& L0, float& L1,
    float& upc, float& upL, float& p_uc, float& p_uL)
{
#pragma unroll 4
    for (int k = 0; k < NSTEPS; ++k) {
        float2 bv = bp[k];                     // uniform broadcast LDS
        const float uc = is_lane0 ? bv.x : upc;
        const float uL = is_lane0 ? bv.y : upL;
        float2 q = qp[k];

        // distances + path-cost terms for both rows (independent, ILP)
        const float dx0 = px0 - q.x, dy0 = py0 - q.y;
        const float dx1 = px1 - q.x, dy1 = py1 - q.y;
        const float d0 = fsqrt_ap(fmaf(dx0, dx0, dy0 * dy0));
        const float d1 = fsqrt_ap(fmaf(dx1, dx1, dy1 * dy1));
        const float e0 = fmaf(fabsf(dx0), sc0, fabsf(dy0) * sc1);
        const float e1 = fmaf(fabsf(dx1), sc0, fabsf(dy1) * sc1);

        const float lc0 = c0, lL0 = L0, lc1 = c1, lL1 = L1;
        // row 0: diag=p_uc, up=uc, left=lc0. tie order: diag, up, left.
        const bool pu0 = (uc <= lc0);
        const float mv0 = pu0 ? uc : lc0;
        const float Lv0 = pu0 ? uL : lL0;
        const bool pd0 = (p_uc <= mv0);
        c0 = d0 + (pd0 ? p_uc : mv0);
        L0 = e0 + (pd0 ? p_uL : Lv0);
        // row 1: diag=lc0(old), up=c0(new), left=lc1
        const bool pu1 = (c0 <= lc1);
        const float mv1 = pu1 ? c0 : lc1;
        const float Lv1 = pu1 ? L0 : lL1;
        const bool pd1 = (lc0 <= mv1);
        c1 = d1 + (pd1 ? lc0 : mv1);
        L1 = e1 + (pd1 ? lL0 : Lv1);

        p_uc = uc; p_uL = uL;

        // branch-free boundary store (lane31 -> real target, others -> sink)
        const int j = s0 + k - 31;
        float2* sta;
        if (GOUT) sta = is_lane31 ? (outp + j) : sinkp;          // STG.64
        else      sta = is_lane31 ? (outp + (j & msk)) : sinkp;  // STS.64
        *sta = make_float2(c1, L1);

        // pipelined lane handoff for next step
        upc = __shfl_up_sync(0xffffffffu, c1, 1);
        upL = __shfl_up_sync(0xffffffffu, L1, 1);
    }
}

__global__ void __launch_bounds__(NTH, 1)
dtw_kernel(const float* __restrict__ preds,
           const float* __restrict__ targs,
           const float* __restrict__ subcoef,
           float* __restrict__ out)
{
    __shared__ float2 sq_full[32 + Tn + 64];   // padded target coords
    __shared__ float2 bnd[NWARP - 1][128];     // 8-deep 16-col chunk rings
    __shared__ float2 sHB[128];                // staged cross-CTA chunks (hi warp0)
    __shared__ float2 sINF[128];               // INF boundary (lo warp0)
    __shared__ float2 sink7[128];              // hi warp7 boundary dump ring
    __shared__ float2 scratch[NTH];            // smem store sink

    const int b    = blockIdx.x >> 1;
    const int hi   = blockIdx.x & 1;
    const int t    = threadIdx.x;
    const int lane = t & 31;
    const int warp = t >> 5;
    const int rowbase = hi * 512 + warp * 64 + lane * 2;

    // ---- stage inputs ----
    const float* tb = targs + (size_t)b * Tn * 4;
    for (int j = t; j < Tn; j += NTH) {
        float4 v = *(const float4*)(tb + j * 4);
        sq_full[32 + j] = make_float2(v.x, v.y);
    }
    if (t < 32)  sq_full[t] = make_float2(0.f, 0.f);
    if (t < 64)  sq_full[32 + Tn + t] = make_float2(0.f, 0.f);
    if (t < 128) sINF[t] = make_float2(INFV, 0.f);

    const float* pb = preds + (size_t)b * Tn * 4;
    float4 p0 = *(const float4*)(pb + (size_t)rowbase * 4);
    float4 p1 = *(const float4*)(pb + (size_t)(rowbase + 1) * 4);
    const float px0 = p0.x, py0 = p0.y, px1 = p1.x, py1 = p1.y;
    const float sc0 = subcoef[0];
    const float sc1 = subcoef[1];

    float c0 = INFV, c1 = INFV, L0 = 0.f, L1 = 0.f;
    if (!hi && t == 0) c0 = 0.f;        // virtual C(0,-1)=0 -> C(0,0)=D(0,0)
    float upc = INFV, upL = 0.f;        // pipelined shfl result
    float p_uc = INFV, p_uL = 0.f;      // previous step's up = diag source

    const bool is_lane0  = (lane == 0);
    const bool is_lane31 = (lane == 31);
    const bool gout = (warp == NWARP - 1) && !hi;

    // lane0 boundary-read source
    const float2* bsrc = (warp == 0) ? (hi ? sHB : sINF) : bnd[warp - 1];
    // lane31 boundary-write target
    float2* outp;
    int msk = 127;
    if (warp < NWARP - 1)      outp = bnd[warp];
    else if (hi)               outp = sink7;
    else                     { outp = g_bnd[b] + 32; msk = -1; }
    float2* sinkp = gout ? &g_dummy[blockIdx.x][lane] : &scratch[t];

    // cross-CTA prefetch state (hi warp0)
    unsigned pf_flag = 0u;
    float2 pf_data = make_float2(INFV, 0.f);
    bool have_pf = false;

    __syncthreads();

    for (int cc = 0; cc < NCHUNK; ++cc) {
        const int s0 = cc * CW;

        // ---- consumer gate: need producer chunk cc+2 FINISHED ----
        if (cc <= 63) {
            if (warp == 0) {
                if (hi) {
                    bool use_pf = false;
                    if (have_pf) {
                        unsigned votes = __ballot_sync(0xffffffffu, pf_flag != 0u);
                        use_pf = ((votes & 0xFFFFu) == 0xFFFFu);
                    }
                    if (use_pf) {
                        if (lane < CW) sHB[((cc & 7) << 4) + lane] = pf_data;
                        if (is_lane0) *(volatile unsigned*)&g_flag[b][cc] = 0u;
                    } else {
                        unsigned* fp = &g_flag[b][cc];
                        if (lane < CW) {
                            while (ld_acq(fp) == 0u) {}         // per-lane acquire
                            float2 v = __ldcg(&g_bnd[b][32 + s0 + lane]);
                            sHB[((cc & 7) << 4) + lane] = v;
                        }
                        __syncwarp();                           // all lanes past spin
                        if (is_lane0) *(volatile unsigned*)fp = 0u;  // self-reset
                    }
                    __syncwarp();                               // sHB visible to body
                    // issue prefetch for chunk cc+1 (resolved during body)
                    have_pf = (cc + 1 <= 63);
                    if (have_pf) {
                        pf_flag = (lane < CW) ? ld_acq(&g_flag[b][cc + 1]) : 1u;
                        if (lane < CW)
                            pf_data = __ldcg(&g_bnd[b][32 + s0 + CW + lane]);
                    }
                }
            } else {
                BARSYNC(warp);              // rendezvous with producer warp-1
            }
        }

        const float2* bp = bsrc + ((cc & 7) << 4);
        const float2* qp = sq_full + 32 + s0 - lane;

        if (gout) {
            if (cc < NCHUNK - 1) run_chunk<CW,     true >(s0, is_lane0, is_lane31, bp, qp, outp, msk, sinkp,
                                     px0, py0, px1, py1, sc0, sc1, c0, c1, L0, L1, upc, upL, p_uc, p_uL);
            else                 run_chunk<CW - 1, true >(s0, is_lane0, is_lane31, bp, qp, outp, msk, sinkp,
                                     px0, py0, px1, py1, sc0, sc1, c0, c1, L0, L1, upc, upL, p_uc, p_uL);
        } else {
            if (cc < NCHUNK - 1) run_chunk<CW,     false>(s0, is_lane0, is_lane31, bp, qp, outp, msk, sinkp,
                                     px0, py0, px1, py1, sc0, sc1, c0, c1, L0, L1, upc, upL, p_uc, p_uL);
            else                 run_chunk<CW - 1, false>(s0, is_lane0, is_lane31, bp, qp, outp, msk, sinkp,
                                     px0, py0, px1, py1, sc0, sc1, c0, c1, L0, L1, upc, upL, p_uc, p_uL);
        }

        // ---- producer release: chunk cc done -> consumer may start cc-2 ----
        if (cc >= 2) {
            if (warp < NWARP - 1) {
                BARSYNC(warp + 1);          // rendezvous with consumer warp+1
            } else if (!hi) {
                if (is_lane31) st_rel(&g_flag[b][cc - 2], 1u);
            }
        }
    }

    // ---- fused reduction: hi CTAs only ----
    if (hi && t == NTH - 1) {
        g_losses[b] = L1;                 // row 1023, col 1023 (last real step)
        __threadfence();
        unsigned old = atomicAdd(&g_count, 1u);
        if (old == Bn - 1) {
            __threadfence();
            float s = 0.f;
            const volatile float* gl = g_losses;
#pragma unroll 8
            for (int i = 0; i < Bn; ++i) s += gl[i];
            out[0] = s;
            g_count = 0;                  // reset for next graph replay
        }
    }
}

extern "C" void kernel_launch(void* const* d_in, const int* in_sizes, int n_in,
                              void* d_out, int out_size)
{
    const float* preds   = (const float*)d_in[0];
    const float* targs   = (const float*)d_in[1];
    const float* subcoef = (const float*)d_in[2];
    float* out = (float*)d_out;

    dtw_kernel<<<2 * Bn, NTH>>>(preds, targs, subcoef, out);
}

// round 13
// speedup vs baseline: 1.0867x; 1.0867x over previous
#include <cuda_runtime.h>

// DTWLoss B=64, T=1024. Warp-pipelined column-sweep DP with fused path loss.
// 2 CTAs per batch (rows 0-511 / 512-1023), 8 warps x 32 lanes x 2 rows each.
// NEW: each lane processes 2 adjacent columns per "superstep" (4 cells),
// amortizing the shfl/LDS latency chain over 2 columns. Lane skew = 2 cols
// per lane (62 total); chunks = 16 supersteps = 32 cols; skew-3 chunk gating
// (consumer chunk cc rendezvous with producer end-of cc+2). Blocking
// rendezvous named barriers (R8-safe). Cross-CTA via gmem float4 boundary +
// self-resetting acquire/release flags. Per-cell math identical to R8.

#define Tn 1024
#define Bn 64
#define NWARP 8
#define NTH 256
#define NCHUNK 34              // 16 supersteps each; last runs 15 (s<=542)
#define INFV 1e30f

__device__ float4   g_bnd[Bn][576];        // lo->hi boundary, float4 per superstep
__device__ unsigned g_flag[Bn][40];        // per-chunk ready flags (self-reset)
__device__ float4   g_dummy[2 * Bn][32];   // gmem store sink (lo warp7, lanes!=31)
__device__ float    g_losses[Bn];
__device__ unsigned g_count;               // zero-init; last CTA resets

__device__ __forceinline__ unsigned ld_acq(const unsigned* p) {
    unsigned v;
    asm volatile("ld.acquire.gpu.u32 %0, [%1];" : "=r"(v) : "l"(p) : "memory");
    return v;
}
__device__ __forceinline__ void st_rel(unsigned* p, unsigned v) {
    asm volatile("st.release.gpu.u32 [%0], %1;" :: "l"(p), "r"(v) : "memory");
}
__device__ __forceinline__ float fsqrt_ap(float x) {
    float r;
    asm("sqrt.approx.f32 %0, %1;" : "=f"(r) : "f"(x));
    return r;
}
#define BARSYNC(id) asm volatile("bar.sync %0, 64;" :: "r"(id) : "memory")

// One DP cell, math identical to R8 (tie order: diag, up, left).
#define CELL(PX, PY, QX, QY, DC, DL, UC, UL, LC, LL, COUT, LOUT)            \
    {                                                                       \
        const float dx_ = (PX) - (QX), dy_ = (PY) - (QY);                   \
        const float d_  = fsqrt_ap(fmaf(dx_, dx_, dy_ * dy_));              \
        const float e_  = fmaf(fabsf(dx_), sc0, fabsf(dy_) * sc1);          \
        const bool  pu_ = ((UC) <= (LC));                                   \
        const float mv_ = pu_ ? (UC) : (LC);                                \
        const float Lv_ = pu_ ? (UL) : (LL);                                \
        const bool  pd_ = ((DC) <= mv_);                                    \
        COUT = d_ + (pd_ ? (DC) : mv_);                                     \
        LOUT = e_ + (pd_ ? (DL) : Lv_);                                     \
    }

// One chunk of NSTEPS supersteps. GOUT: lane31 stores go to gmem (lo warp7).
template<int NSTEPS, bool GOUT>
__device__ __forceinline__ void run_chunk(
    int sbase,                       // first superstep of chunk (16*cc)
    bool is_lane0, bool is_lane31,
    const float4* __restrict__ bsrc, // 64-slot ring (or sHB/sINF)
    const float4* __restrict__ qp,   // sq4 + 32 + 16*cc - lane
    float4* outp, float4* sinkp, int gabs,   // gabs: absolute gmem indexing
    float px0, float py0, float px1, float py1, float sc0, float sc1,
    float& c0, float& c1, float& L0, float& L1,
    float& upcA, float& upLA, float& upcB, float& upLB,
    float& pBc, float& pBL)
{
    const int rbase = (sbase + 31) & 63;     // ring read base
#pragma unroll 5
    for (int k = 0; k < NSTEPS; ++k) {
        const float4 bv = bsrc[(rbase + k) & 63];   // uniform broadcast LDS.128
        const float ucA = is_lane0 ? bv.x : upcA;
        const float uLA = is_lane0 ? bv.y : upLA;
        const float ucB = is_lane0 ? bv.z : upcB;
        const float uLB = is_lane0 ? bv.w : upLB;
        const float4 q = qp[k];                     // cols A,B coords

        // column A
        const float lc0 = c0, lL0 = L0, lc1 = c1, lL1 = L1;
        CELL(px0, py0, q.x, q.y, pBc, pBL, ucA, uLA, lc0, lL0, c0, L0)   // r0,A
        CELL(px1, py1, q.x, q.y, lc0, lL0, c0,  L0,  lc1, lL1, c1, L1)   // r1,A
        const float c0A = c0, L0A = L0, c1A = c1, L1A = L1;
        // column B
        CELL(px0, py0, q.z, q.w, ucA, uLA, ucB, uLB, c0A, L0A, c0, L0)   // r0,B
        CELL(px1, py1, q.z, q.w, c0A, L0A, c0,  L0,  c1A, L1A, c1, L1)   // r1,B
        pBc = ucB; pBL = uLB;

        // branch-free boundary store: lane31 -> real target, others -> sink
        const int s = sbase + k;
        float4* sta;
        if (GOUT) sta = is_lane31 ? (outp + s)        : sinkp;   // STG.128
        else      sta = is_lane31 ? (outp + (s & 63)) : sinkp;   // STS.128
        *sta = make_float4(c1A, L1A, c1, L1);

        // lane handoff for next superstep
        upcA = __shfl_up_sync(0xffffffffu, c1A, 1);
        upLA = __shfl_up_sync(0xffffffffu, L1A, 1);
        upcB = __shfl_up_sync(0xffffffffu, c1, 1);
        upLB = __shfl_up_sync(0xffffffffu, L1, 1);
    }
    (void)gabs;
}

__global__ void __launch_bounds__(NTH, 1)
dtw_kernel(const float* __restrict__ preds,
           const float* __restrict__ targs,
           const float* __restrict__ subcoef,
           float* __restrict__ out)
{
    __shared__ float4 sq4[608];                // packed q col-pairs, offset 32
    __shared__ float4 bnd[NWARP - 1][64];      // 4-chunk superstep rings
    __shared__ float4 sHB[64];                 // staged cross-CTA ring (hi warp0)
    __shared__ float4 sINF[64];                // INF boundary (lo warp0)
    __shared__ float4 sink7[64];               // hi warp7 boundary dump ring
    __shared__ float4 scratch[NTH];            // smem store sink

    const int b    = blockIdx.x >> 1;
    const int hi   = blockIdx.x & 1;
    const int t    = threadIdx.x;
    const int lane = t & 31;
    const int warp = t >> 5;
    const int rowbase = hi * 512 + warp * 64 + lane * 2;

    // ---- stage inputs ----
    const float4* tb4 = (const float4*)(targs + (size_t)b * Tn * 4);
    for (int i = t; i < 512; i += NTH) {
        float4 v0 = tb4[2 * i];
        float4 v1 = tb4[2 * i + 1];
        sq4[32 + i] = make_float4(v0.x, v0.y, v1.x, v1.y);
    }
    if (t < 32) sq4[t] = make_float4(0.f, 0.f, 0.f, 0.f);
    if (t < 64) sq4[544 + t] = make_float4(0.f, 0.f, 0.f, 0.f);
    if (t < 64) sINF[t] = make_float4(INFV, 0.f, INFV, 0.f);

    const float* pb = preds + (size_t)b * Tn * 4;
    float4 p0 = *(const float4*)(pb + (size_t)rowbase * 4);
    float4 p1 = *(const float4*)(pb + (size_t)(rowbase + 1) * 4);
    const float px0 = p0.x, py0 = p0.y, px1 = p1.x, py1 = p1.y;
    const float sc0 = subcoef[0];
    const float sc1 = subcoef[1];

    float c0 = INFV, c1 = INFV, L0 = 0.f, L1 = 0.f;
    if (!hi && t == 0) c0 = 0.f;        // virtual C(0,-1)=0 -> C(0,0)=D(0,0)
    float upcA = INFV, upLA = 0.f, upcB = INFV, upLB = 0.f;
    float pBc = INFV, pBL = 0.f;        // retained col J-1 boundary (diag source)

    const bool is_lane0  = (lane == 0);
    const bool is_lane31 = (lane == 31);
    const bool gout = (warp == NWARP - 1) && !hi;

    const float4* bsrc = (warp == 0) ? (hi ? sHB : sINF) : bnd[warp - 1];
    float4* outp;
    if (warp < NWARP - 1)      outp = bnd[warp];
    else if (hi)               outp = sink7;
    else                       outp = g_bnd[b];      // absolute superstep index
    float4* sinkp = gout ? &g_dummy[blockIdx.x][lane] : &scratch[t];

    __syncthreads();

    for (int cc = 0; cc < NCHUNK; ++cc) {
        const int sbase = cc * 16;

        // ---- consumer gate: need producer chunk cc+2 FINISHED (skew-3) ----
        if (cc <= 31) {
            if (warp == 0) {
                if (hi) {
                    unsigned* fp = &g_flag[b][cc];
                    if (is_lane0) { while (ld_acq(fp) == 0u) {} }
                    __syncwarp();
                    if (lane < 16) {
                        const int s = sbase + 31 + lane;          // <= 542
                        float4 v = __ldcg(&g_bnd[b][s]);
                        sHB[s & 63] = v;
                    }
                    __syncwarp();
                    if (is_lane0) *(volatile unsigned*)fp = 0u;   // self-reset
                    __syncwarp();
                }
            } else {
                BARSYNC(warp);              // rendezvous with producer warp-1
            }
        }

        const float4* qp = sq4 + 32 + sbase - lane;

        if (gout) {
            if (cc < NCHUNK - 1) run_chunk<16, true >(sbase, is_lane0, is_lane31, bsrc, qp, outp, sinkp, 1,
                                     px0, py0, px1, py1, sc0, sc1, c0, c1, L0, L1, upcA, upLA, upcB, upLB, pBc, pBL);
            else                 run_chunk<15, true >(sbase, is_lane0, is_lane31, bsrc, qp, outp, sinkp, 1,
                                     px0, py0, px1, py1, sc0, sc1, c0, c1, L0, L1, upcA, upLA, upcB, upLB, pBc, pBL);
        } else {
            if (cc < NCHUNK - 1) run_chunk<16, false>(sbase, is_lane0, is_lane31, bsrc, qp, outp, sinkp, 0,
                                     px0, py0, px1, py1, sc0, sc1, c0, c1, L0, L1, upcA, upLA, upcB, upLB, pBc, pBL);
            else                 run_chunk<15, false>(sbase, is_lane0, is_lane31, bsrc, qp, outp, sinkp, 0,
                                     px0, py0, px1, py1, sc0, sc1, c0, c1, L0, L1, upcA, upLA, upcB, upLB, pBc, pBL);
        }

        // ---- producer release: chunk cc done -> consumer may start cc-2 ----
        if (cc >= 2) {
            if (warp < NWARP - 1) {
                BARSYNC(warp + 1);          // rendezvous with consumer warp+1
            } else if (!hi) {
                if (is_lane31) st_rel(&g_flag[b][cc - 2], 1u);
            }
        }
    }

    // ---- fused reduction: hi CTAs only ----
    if (hi && t == NTH - 1) {
        g_losses[b] = L1;                 // row 1023, col 1023 (superstep 542, col B)
        __threadfence();
        unsigned old = atomicAdd(&g_count, 1u);
        if (old == Bn - 1) {
            __threadfence();
            float s = 0.f;
            const volatile float* gl = g_losses;
#pragma unroll 8
            for (int i = 0; i < Bn; ++i) s += gl[i];
            out[0] = s;
            g_count = 0;                  // reset for next graph replay
        }
    }
}

extern "C" void kernel_launch(void* const* d_in, const int* in_sizes, int n_in,
                              void* d_out, int out_size)
{
    const float* preds   = (const float*)d_in[0];
    const float* targs   = (const float*)d_in[1];
    const float* subcoef = (const float*)d_in[2];
    float* out = (float*)d_out;

    dtw_kernel<<<2 * Bn, NTH>>>(preds, targs, subcoef, out);
}

// round 14
// speedup vs baseline: 1.2152x; 1.1182x over previous
#include <cuda_runtime.h>

// DTWLoss B=64, T=1024. Warp-pipelined column-sweep DP with fused path loss.
// 2 CTAs per batch (rows 0-511 / 512-1023), 8 warps x 32 lanes x 2 rows each.
// 16-stage pipeline: intra-CTA via smem rings + named barriers (R8 topology,
// CW=32, blocking rendezvous), cross-CTA via gmem boundary + self-resetting
// acquire/release flags. ONLY change vs R8: c-recurrence uses FMNMX chains
// (c = d + fmin(diag, fmin(up,left))); L tie-break selects identical to R8.

#define Tn 1024
#define Bn 64
#define CW 32
#define NWARP 8
#define NTH 256
#define INFV 1e30f

__device__ float2   g_bnd[Bn][Tn + 64];    // row-511 boundary; +32 front pad
__device__ unsigned g_flag[Bn][32];        // per-chunk ready flags (self-reset)
__device__ float2   g_dummy[2 * Bn][32];   // gmem store sink (lo warp7, lanes!=31)
__device__ float    g_losses[Bn];
__device__ unsigned g_count;               // zero-init; last CTA resets

__device__ __forceinline__ unsigned ld_acq(const unsigned* p) {
    unsigned v;
    asm volatile("ld.acquire.gpu.u32 %0, [%1];" : "=r"(v) : "l"(p) : "memory");
    return v;
}
__device__ __forceinline__ void st_rel(unsigned* p, unsigned v) {
    asm volatile("st.release.gpu.u32 [%0], %1;" :: "l"(p), "r"(v) : "memory");
}
__device__ __forceinline__ float fsqrt_ap(float x) {
    float r;
    asm("sqrt.approx.f32 %0, %1;" : "=f"(r) : "f"(x));
    return r;
}
#define BARSYNC(id) asm volatile("bar.sync %0, 64;" :: "r"(id) : "memory")

// One 32(or 31)-step chunk. GOUT: boundary store goes to gmem (lo warp7).
template<int NSTEPS, bool GOUT>
__device__ __forceinline__ void run_chunk(
    int s0, bool is_lane0, bool is_lane31,
    const float2* __restrict__ bp, const float2* __restrict__ qp,
    float2* outp, int msk, float2* sinkp,
    float px0, float py0, float px1, float py1, float sc0, float sc1,
    float& c0, float& c1, float& L0, float& L1,
    float& upc, float& upL, float& p_uc, float& p_uL)
{
#pragma unroll 4
    for (int k = 0; k < NSTEPS; ++k) {
        float2 bv = bp[k];                     // uniform broadcast LDS
        const float uc = is_lane0 ? bv.x : upc;
        const float uL = is_lane0 ? bv.y : upL;
        float2 q = qp[k];

        // distances + path-cost terms for both rows (independent, ILP)
        const float dx0 = px0 - q.x, dy0 = py0 - q.y;
        const float dx1 = px1 - q.x, dy1 = py1 - q.y;
        const float d0 = fsqrt_ap(fmaf(dx0, dx0, dy0 * dy0));
        const float d1 = fsqrt_ap(fmaf(dx1, dx1, dy1 * dy1));
        const float e0 = fmaf(fabsf(dx0), sc0, fabsf(dy0) * sc1);
        const float e1 = fmaf(fabsf(dx1), sc0, fabsf(dy1) * sc1);

        const float lc0 = c0, lL0 = L0, lc1 = c1, lL1 = L1;
        // row 0: diag=p_uc, up=uc, left=lc0. FMNMX chain for c; L selects as R8.
        const float mul0 = fminf(uc, lc0);
        const bool  pu0  = (uc <= lc0);
        const float Lv0  = pu0 ? uL : lL0;
        const bool  pd0  = (p_uc <= mul0);
        c0 = d0 + fminf(p_uc, mul0);
        L0 = e0 + (pd0 ? p_uL : Lv0);
        // row 1: diag=lc0(old), up=c0(new), left=lc1
        const float mul1 = fminf(c0, lc1);
        const bool  pu1  = (c0 <= lc1);
        const float Lv1  = pu1 ? L0 : lL1;
        const bool  pd1  = (lc0 <= mul1);
        c1 = d1 + fminf(lc0, mul1);
        L1 = e1 + (pd1 ? lL0 : Lv1);

        p_uc = uc; p_uL = uL;

        // branch-free boundary store (lane31 -> real target, others -> sink)
        const int j = s0 + k - 31;
        float2* sta;
        if (GOUT) sta = is_lane31 ? (outp + j) : sinkp;          // STG.64
        else      sta = is_lane31 ? (outp + (j & msk)) : sinkp;  // STS.64
        *sta = make_float2(c1, L1);

        // pipelined lane handoff for next step
        upc = __shfl_up_sync(0xffffffffu, c1, 1);
        upL = __shfl_up_sync(0xffffffffu, L1, 1);
    }
}

__global__ void __launch_bounds__(NTH, 1)
dtw_kernel(const float* __restrict__ preds,
           const float* __restrict__ targs,
           const float* __restrict__ subcoef,
           float* __restrict__ out)
{
    __shared__ float2 sq_full[32 + Tn + 64];   // padded target coords
    __shared__ float2 bnd[NWARP - 1][128];     // 4-deep chunk rings (warp w -> w+1)
    __shared__ float2 sHB[128];                // staged cross-CTA chunks (hi warp0)
    __shared__ float2 sINF[128];               // INF boundary (lo warp0)
    __shared__ float2 sink7[32];               // hi warp7 boundary dump ring
    __shared__ float2 scratch[NTH];            // smem store sink

    const int b    = blockIdx.x >> 1;
    const int hi   = blockIdx.x & 1;
    const int t    = threadIdx.x;
    const int lane = t & 31;
    const int warp = t >> 5;
    const int rowbase = hi * 512 + warp * 64 + lane * 2;

    // ---- stage inputs ----
    const float* tb = targs + (size_t)b * Tn * 4;
    for (int j = t; j < Tn; j += NTH) {
        float4 v = *(const float4*)(tb + j * 4);
        sq_full[32 + j] = make_float2(v.x, v.y);
    }
    if (t < 32)  sq_full[t] = make_float2(0.f, 0.f);
    if (t < 64)  sq_full[32 + Tn + t] = make_float2(0.f, 0.f);
    if (t < 128) sINF[t] = make_float2(INFV, 0.f);

    const float* pb = preds + (size_t)b * Tn * 4;
    float4 p0 = *(const float4*)(pb + (size_t)rowbase * 4);
    float4 p1 = *(const float4*)(pb + (size_t)(rowbase + 1) * 4);
    const float px0 = p0.x, py0 = p0.y, px1 = p1.x, py1 = p1.y;
    const float sc0 = subcoef[0];
    const float sc1 = subcoef[1];

    float c0 = INFV, c1 = INFV, L0 = 0.f, L1 = 0.f;
    if (!hi && t == 0) c0 = 0.f;        // virtual C(0,-1)=0 -> C(0,0)=D(0,0)
    float upc = INFV, upL = 0.f;        // pipelined shfl result
    float p_uc = INFV, p_uL = 0.f;      // previous step's up = diag source

    const bool is_lane0  = (lane == 0);
    const bool is_lane31 = (lane == 31);
    const bool gout = (warp == NWARP - 1) && !hi;

    // lane0 boundary-read source
    const float2* bsrc = (warp == 0) ? (hi ? sHB : sINF) : bnd[warp - 1];
    // lane31 boundary-write target
    float2* outp;
    int msk;
    if (warp < NWARP - 1) { outp = bnd[warp]; msk = 127; }
    else if (hi)          { outp = sink7;     msk = 31; }
    else                  { outp = g_bnd[b] + 32; msk = -1; }
    float2* sinkp = gout ? &g_dummy[blockIdx.x][lane] : &scratch[t];

    __syncthreads();

    for (int cc = 0; cc <= 32; ++cc) {
        const int s0 = cc * CW;
        // ---- prologue: consumer waits for producer stage ----
        if (cc < 32) {
            if (warp == 0) {
                if (hi) {
                    unsigned* fp = &g_flag[b][cc];
                    if (is_lane0) { while (ld_acq(fp) == 0u) {} }
                    __syncwarp();
                    float2 v = __ldcg(&g_bnd[b][32 + s0 + lane]);
                    sHB[((cc & 3) << 5) + lane] = v;
                    if (is_lane0) *(volatile unsigned*)fp = 0u;   // self-reset
                    __syncwarp();
                }
            } else {
                BARSYNC(warp);
            }
        }

        const float2* bp = bsrc + ((cc & 3) << 5);
        const float2* qp = sq_full + 32 + s0 - lane;

        if (gout) {
            if (cc < 32) run_chunk<32, true >(s0, is_lane0, is_lane31, bp, qp, outp, msk, sinkp,
                                              px0, py0, px1, py1, sc0, sc1, c0, c1, L0, L1, upc, upL, p_uc, p_uL);
            else         run_chunk<31, true >(s0, is_lane0, is_lane31, bp, qp, outp, msk, sinkp,
                                              px0, py0, px1, py1, sc0, sc1, c0, c1, L0, L1, upc, upL, p_uc, p_uL);
        } else {
            if (cc < 32) run_chunk<32, false>(s0, is_lane0, is_lane31, bp, qp, outp, msk, sinkp,
                                              px0, py0, px1, py1, sc0, sc1, c0, c1, L0, L1, upc, upL, p_uc, p_uL);
            else         run_chunk<31, false>(s0, is_lane0, is_lane31, bp, qp, outp, msk, sinkp,
                                              px0, py0, px1, py1, sc0, sc1, c0, c1, L0, L1, upc, upL, p_uc, p_uL);
        }

        // ---- epilogue: producer release (chunk cc done -> consumer may run cc-1) ----
        if (cc >= 1) {
            if (warp < NWARP - 1) {
                BARSYNC(warp + 1);
            } else if (!hi) {
                if (is_lane31) st_rel(&g_flag[b][cc - 1], 1u);
            }
        }
    }

    // ---- fused reduction: hi CTAs only ----
    if (hi && t == NTH - 1) {
        g_losses[b] = L1;                 // row 1023, col 1023 (last real step)
        __threadfence();
        unsigned old = atomicAdd(&g_count, 1u);
        if (old == Bn - 1) {
            __threadfence();
            float s = 0.f;
            const volatile float* gl = g_losses;
#pragma unroll 8
            for (int i = 0; i < Bn; ++i) s += gl[i];
            out[0] = s;
            g_count = 0;                  // reset for next graph replay
        }
    }
}

extern "C" void kernel_launch(void* const* d_in, const int* in_sizes, int n_in,
                              void* d_out, int out_size)
{
    const float* preds   = (const float*)d_in[0];
    const float* targs   = (const float*)d_in[1];
    const float* subcoef = (const float*)d_in[2];
    float* out = (float*)d_out;

    dtw_kernel<<<2 * Bn, NTH>>>(preds, targs, subcoef, out);
}